// round 7
// baseline (speedup 1.0000x reference)
#include <cuda_runtime.h>
#include <cuda_fp16.h>
#include <cstdint>

#define BDIM 8
#define SDIM 4096
#define EDIM 256
#define HDIM 4
#define DK   64
#define MTOT (BDIM * SDIM)   // 32768

// ---------------- scratch (device globals; no runtime alloc) -------------------
__device__ __half g_xh[(size_t)MTOT * EDIM];
__device__ __half g_xl[(size_t)MTOT * EDIM];
__device__ __half g_yh[(size_t)MTOT * EDIM];
__device__ __half g_yl[(size_t)MTOT * EDIM];
__device__ float  g_q[(size_t)MTOT * EDIM];
__device__ float  g_k[(size_t)MTOT * EDIM];
__device__ float  g_v[(size_t)MTOT * EDIM];
__device__ __half g_wh[4][EDIM * EDIM];
__device__ __half g_wl[4][EDIM * EDIM];

// ---------------- helpers ------------------------------------------------------
__device__ __forceinline__ uint32_t smem_u32(const void* p) {
    uint32_t a;
    asm("{ .reg .u64 t; cvta.to.shared.u64 t, %1; cvt.u32.u64 %0, t; }" : "=r"(a) : "l"(p));
    return a;
}

#define CP_ASYNC16(smem, gmem) \
    asm volatile("cp.async.cg.shared.global [%0], [%1], 16;" :: "r"(smem), "l"(gmem))
#define CP_ASYNC_COMMIT() asm volatile("cp.async.commit_group;")
#define CP_ASYNC_WAIT(n)  asm volatile("cp.async.wait_group %0;" :: "n"(n))

#define LDMATRIX_X4(r0, r1, r2, r3, addr) \
    asm volatile("ldmatrix.sync.aligned.m8n8.x4.shared.b16 {%0,%1,%2,%3}, [%4];" \
        : "=r"(r0), "=r"(r1), "=r"(r2), "=r"(r3) : "r"(addr))

#define MMA16816(c, a, b0, b1) \
    asm volatile("mma.sync.aligned.m16n8k16.row.col.f32.f16.f16.f32 " \
        "{%0,%1,%2,%3}, {%4,%5,%6,%7}, {%8,%9}, {%0,%1,%2,%3};" \
        : "+f"((c)[0]), "+f"((c)[1]), "+f"((c)[2]), "+f"((c)[3]) \
        : "r"((a)[0]), "r"((a)[1]), "r"((a)[2]), "r"((a)[3]), "r"(b0), "r"(b1))

// ---------------- split: fp32 -> fp16 hi + fp16 lo ------------------------------
__device__ __forceinline__ void split4(float4 v, uint2& H, uint2& L) {
    __half h0 = __float2half_rn(v.x), h1 = __float2half_rn(v.y);
    __half h2 = __float2half_rn(v.z), h3 = __float2half_rn(v.w);
    __half2 ph0{h0, h1}, ph1{h2, h3};
    __half2 pl0{__float2half_rn(v.x - __half2float(h0)),
                __float2half_rn(v.y - __half2float(h1))};
    __half2 pl1{__float2half_rn(v.z - __half2float(h2)),
                __float2half_rn(v.w - __half2float(h3))};
    H.x = *(uint32_t*)&ph0; H.y = *(uint32_t*)&ph1;
    L.x = *(uint32_t*)&pl0; L.y = *(uint32_t*)&pl1;
}

#define X4   (MTOT * EDIM / 4)
#define W4   (EDIM * EDIM / 4)
#define ALL4 (X4 + 4 * W4)

__global__ void split_all_kernel(const float4* __restrict__ x,
                                 const float4* __restrict__ w0, const float4* __restrict__ w1,
                                 const float4* __restrict__ w2, const float4* __restrict__ w3,
                                 uint2* __restrict__ xhi, uint2* __restrict__ xlo,
                                 uint2* __restrict__ whi, uint2* __restrict__ wlo)
{
    int i = blockIdx.x * blockDim.x + threadIdx.x;
    if (i >= ALL4) return;
    uint2 H, L;
    if (i < X4) {
        split4(x[i], H, L);
        xhi[i] = H; xlo[i] = L;
    } else {
        int j = i - X4;
        int which = j >> 14;
        int idx = j & 16383;
        const float4* src = which == 0 ? w0 : which == 1 ? w1 : which == 2 ? w2 : w3;
        split4(src[idx], H, L);
        whi[j] = H; wlo[j] = L;
    }
}

// ---------------- HMMA GEMM ------------------------------------------------------
#define BM 128
#define BN 128
#define BK 32
#define NKC (EDIM / BK)             // 8
#define GT 256
#define LDA 40
#define TILE (BM * LDA)             // 5120 halves
#define STAGE (4 * TILE)
#define SMEM_BYTES (2 * STAGE * 2 + 1024)

__device__ __forceinline__ void load_stage(uint32_t st,
                                           const __half* __restrict__ Ah,
                                           const __half* __restrict__ Al,
                                           const __half* __restrict__ Wh,
                                           const __half* __restrict__ Wl,
                                           int m0, int n0, int k0, int tid)
{
#pragma unroll
    for (int i = 0; i < 2; i++) {
        const int c = tid + i * GT;
        const int row = c >> 2;
        const int col = (c & 3) << 3;
        const uint32_t soff = (uint32_t)(row * LDA + col) * 2;
        const size_t aoff = (size_t)(m0 + row) * EDIM + k0 + col;
        const size_t woff = (size_t)(n0 + row) * EDIM + k0 + col;
        CP_ASYNC16(st + soff, Ah + aoff);
        CP_ASYNC16(st + TILE * 2 + soff, Al + aoff);
        CP_ASYNC16(st + 2 * TILE * 2 + soff, Wh + woff);
        CP_ASYNC16(st + 3 * TILE * 2 + soff, Wl + woff);
    }
}

__global__ __launch_bounds__(GT, 2)
void hmma_gemm_kernel(const __half* __restrict__ Ah,
                      const __half* __restrict__ Al,
                      const __half* __restrict__ Wh_all,
                      const __half* __restrict__ Wl_all,
                      const float* __restrict__ b0p,
                      const float* __restrict__ b1p,
                      const float* __restrict__ b2p,
                      float* __restrict__ o0,
                      float* __restrict__ o1,
                      float* __restrict__ o2,
                      int wbase)
{
    extern __shared__ __half smem[];
    const uint32_t sb = smem_u32(smem);
    float* sbias = (float*)(smem + 2 * STAGE);

    const int tid = threadIdx.x;
    const int wid = tid >> 5;
    const int lane = tid & 31;
    const int sel = blockIdx.x >> 1;
    const int n0 = (blockIdx.x & 1) * BN;
    const int m0 = blockIdx.y * BM;
    const int warp_m = (wid & 3) * 32;
    const int warp_n = (wid >> 2) * 64;

    const __half* Wh = Wh_all + (size_t)(wbase + sel) * EDIM * EDIM;
    const __half* Wl = Wl_all + (size_t)(wbase + sel) * EDIM * EDIM;
    const float* bias = sel == 0 ? b0p : (sel == 1 ? b1p : b2p);
    float* C = sel == 0 ? o0 : (sel == 1 ? o1 : o2);

    load_stage(sb, Ah, Al, Wh, Wl, m0, n0, 0, tid);
    CP_ASYNC_COMMIT();
    load_stage(sb + STAGE * 2, Ah, Al, Wh, Wl, m0, n0, BK, tid);
    CP_ASYNC_COMMIT();
    if (tid < 128) sbias[tid] = bias[n0 + tid];

    float acc[2][8][4];
#pragma unroll
    for (int i = 0; i < 2; i++)
#pragma unroll
        for (int j = 0; j < 8; j++)
#pragma unroll
            for (int r = 0; r < 4; r++) acc[i][j][r] = 0.0f;

    for (int kc = 0; kc < NKC; kc++) {
        if (kc < NKC - 1) CP_ASYNC_WAIT(1); else CP_ASYNC_WAIT(0);
        __syncthreads();

        const uint32_t st = sb + (kc & 1) * STAGE * 2;
        const uint32_t sAh = st;
        const uint32_t sAl = st + TILE * 2;
        const uint32_t sWh = st + 2 * TILE * 2;
        const uint32_t sWl = st + 3 * TILE * 2;

#pragma unroll
        for (int ks = 0; ks < BK / 16; ks++) {
            const int k = ks * 16;
            uint32_t ah[2][4], al[2][4];
#pragma unroll
            for (int mf = 0; mf < 2; mf++) {
                const uint32_t off =
                    (uint32_t)((warp_m + mf * 16 + (lane & 15)) * LDA + k + ((lane >> 4) << 3)) * 2;
                LDMATRIX_X4(ah[mf][0], ah[mf][1], ah[mf][2], ah[mf][3], sAh + off);
                LDMATRIX_X4(al[mf][0], al[mf][1], al[mf][2], al[mf][3], sAl + off);
            }
#pragma unroll
            for (int np = 0; np < 4; np++) {
                const uint32_t boff =
                    (uint32_t)((warp_n + np * 16 + (lane & 7) + ((lane >> 4) << 3)) * LDA
                               + k + (((lane >> 3) & 1) << 3)) * 2;
                uint32_t bh[4], bl[4];
                LDMATRIX_X4(bh[0], bh[1], bh[2], bh[3], sWh + boff);
                LDMATRIX_X4(bl[0], bl[1], bl[2], bl[3], sWl + boff);
                // Round-robin across the 4 independent accumulators so that
                // same-accumulator MMAs are 4 apart (breaks RAW chains).
                float* a00 = acc[0][np * 2];
                float* a01 = acc[0][np * 2 + 1];
                float* a10 = acc[1][np * 2];
                float* a11 = acc[1][np * 2 + 1];
                // term 1: ah * bh
                MMA16816(a00, ah[0], bh[0], bh[1]);
                MMA16816(a01, ah[0], bh[2], bh[3]);
                MMA16816(a10, ah[1], bh[0], bh[1]);
                MMA16816(a11, ah[1], bh[2], bh[3]);
                // term 2: ah * bl
                MMA16816(a00, ah[0], bl[0], bl[1]);
                MMA16816(a01, ah[0], bl[2], bl[3]);
                MMA16816(a10, ah[1], bl[0], bl[1]);
                MMA16816(a11, ah[1], bl[2], bl[3]);
                // term 3: al * bh
                MMA16816(a00, al[0], bh[0], bh[1]);
                MMA16816(a01, al[0], bh[2], bh[3]);
                MMA16816(a10, al[1], bh[0], bh[1]);
                MMA16816(a11, al[1], bh[2], bh[3]);
            }
        }
        __syncthreads();
        if (kc + 2 < NKC) {
            load_stage(st, Ah, Al, Wh, Wl, m0, n0, (kc + 2) * BK, tid);
            CP_ASYNC_COMMIT();
        }
    }

    // epilogue: C = acc + bias (bias from smem)
#pragma unroll
    for (int mf = 0; mf < 2; mf++) {
        const int r0 = m0 + warp_m + mf * 16 + (lane >> 2);
#pragma unroll
        for (int nf = 0; nf < 8; nf++) {
            const int colL = warp_n + nf * 8 + (lane & 3) * 2;
            const float b0 = sbias[colL], b1 = sbias[colL + 1];
            const int col = n0 + colL;
            float2 v0{acc[mf][nf][0] + b0, acc[mf][nf][1] + b1};
            float2 v1{acc[mf][nf][2] + b0, acc[mf][nf][3] + b1};
            *(float2*)(C + (size_t)r0 * EDIM + col) = v0;
            *(float2*)(C + (size_t)(r0 + 8) * EDIM + col) = v1;
        }
    }
}

// ---------------- attention over heads; fused y -> (yh, yl) fp16 split ----------
__global__ __launch_bounds__(256)
void attn_heads_kernel(const float* __restrict__ q,
                       const float* __restrict__ k,
                       const float* __restrict__ v,
                       __half* __restrict__ yh,
                       __half* __restrict__ yl)
{
    const int t = blockIdx.x * 8 + (threadIdx.x >> 5);
    const int lane = threadIdx.x & 31;

    const float2* qt = (const float2*)(q + (size_t)t * EDIM) + lane;
    const float2* kt = (const float2*)(k + (size_t)t * EDIM) + lane;
    const float2* vt = (const float2*)(v + (size_t)t * EDIM) + lane;

    float2 qv[HDIM], kv[HDIM], vv[HDIM];
#pragma unroll
    for (int h = 0; h < HDIM; h++) {
        qv[h] = qt[h * 32];
        kv[h] = kt[h * 32];
        vv[h] = vt[h * 32];
    }

    float s[HDIM][HDIM];
#pragma unroll
    for (int h = 0; h < HDIM; h++)
#pragma unroll
        for (int g = 0; g < HDIM; g++) {
            float p = qv[h].x * kv[g].x + qv[h].y * kv[g].y;
#pragma unroll
            for (int off = 16; off > 0; off >>= 1)
                p += __shfl_xor_sync(0xFFFFFFFFu, p, off);
            s[h][g] = p * 0.125f;
        }

    float p[HDIM][HDIM];
#pragma unroll
    for (int h = 0; h < HDIM; h++) {
        float m = s[h][0];
#pragma unroll
        for (int g = 1; g < HDIM; g++) m = fmaxf(m, s[h][g]);
        float sum = 0.0f;
#pragma unroll
        for (int g = 0; g < HDIM; g++) { p[h][g] = __expf(s[h][g] - m); sum += p[h][g]; }
        const float inv = 1.0f / sum;
#pragma unroll
        for (int g = 0; g < HDIM; g++) p[h][g] *= inv;
    }

    __half2* yhp = (__half2*)(yh + (size_t)t * EDIM) + lane;
    __half2* ylp = (__half2*)(yl + (size_t)t * EDIM) + lane;
#pragma unroll
    for (int h = 0; h < HDIM; h++) {
        float ax = 0.0f, ay = 0.0f;
#pragma unroll
        for (int g = 0; g < HDIM; g++) {
            ax = fmaf(p[h][g], vv[g].x, ax);
            ay = fmaf(p[h][g], vv[g].y, ay);
        }
        __half hx = __float2half_rn(ax), hy = __float2half_rn(ay);
        yhp[h * 32] = __half2{hx, hy};
        ylp[h * 32] = __half2{__float2half_rn(ax - __half2float(hx)),
                              __float2half_rn(ay - __half2float(hy))};
    }
}

// ---------------- launch --------------------------------------------------------
extern "C" void kernel_launch(void* const* d_in, const int* in_sizes, int n_in,
                              void* d_out, int out_size)
{
    const float* x  = (const float*)d_in[0];
    const float* Wq = (const float*)d_in[1];
    const float* bq = (const float*)d_in[2];
    const float* Wk = (const float*)d_in[3];
    const float* bk = (const float*)d_in[4];
    const float* Wv = (const float*)d_in[5];
    const float* bv = (const float*)d_in[6];
    const float* Wo = (const float*)d_in[7];
    const float* bo = (const float*)d_in[8];
    float* out = (float*)d_out;

    __half *xh, *xl, *yh, *yl;
    float *q, *k, *v;
    __half (*wh)[EDIM * EDIM], (*wl)[EDIM * EDIM];
    cudaGetSymbolAddress((void**)&xh, g_xh);
    cudaGetSymbolAddress((void**)&xl, g_xl);
    cudaGetSymbolAddress((void**)&yh, g_yh);
    cudaGetSymbolAddress((void**)&yl, g_yl);
    cudaGetSymbolAddress((void**)&q, g_q);
    cudaGetSymbolAddress((void**)&k, g_k);
    cudaGetSymbolAddress((void**)&v, g_v);
    cudaGetSymbolAddress((void**)&wh, g_wh);
    cudaGetSymbolAddress((void**)&wl, g_wl);

    cudaFuncSetAttribute(hmma_gemm_kernel,
                         cudaFuncAttributeMaxDynamicSharedMemorySize, SMEM_BYTES);

    split_all_kernel<<<(ALL4 + 255) / 256, 256>>>(
        (const float4*)x, (const float4*)Wq, (const float4*)Wk,
        (const float4*)Wv, (const float4*)Wo,
        (uint2*)xh, (uint2*)xl, (uint2*)wh[0], (uint2*)wl[0]);

    {
        dim3 grid(6, MTOT / BM);
        hmma_gemm_kernel<<<grid, GT, SMEM_BYTES>>>(
            xh, xl, wh[0], wl[0], bq, bk, bv, q, k, v, 0);
    }

    attn_heads_kernel<<<MTOT / 8, 256>>>(q, k, v, yh, yl);

    {
        dim3 grid(2, MTOT / BM);
        hmma_gemm_kernel<<<grid, GT, SMEM_BYTES>>>(
            yh, yl, wh[0], wl[0], bo, bo, bo, out, out, out, 3);
    }
}

// round 8
// speedup vs baseline: 1.0428x; 1.0428x over previous
#include <cuda_runtime.h>
#include <cuda_fp16.h>
#include <cstdint>

#define BDIM 8
#define SDIM 4096
#define EDIM 256
#define HDIM 4
#define DK   64
#define MTOT (BDIM * SDIM)   // 32768

// ---------------- scratch (device globals; no runtime alloc) -------------------
__device__ __half g_xh[(size_t)MTOT * EDIM];
__device__ __half g_xl[(size_t)MTOT * EDIM];
__device__ __half g_yh[(size_t)MTOT * EDIM];
__device__ __half g_yl[(size_t)MTOT * EDIM];
__device__ float  g_q[(size_t)MTOT * EDIM];
__device__ float  g_k[(size_t)MTOT * EDIM];
__device__ float  g_v[(size_t)MTOT * EDIM];
__device__ __half g_wh[4][EDIM * EDIM];
__device__ __half g_wl[4][EDIM * EDIM];

// ---------------- helpers ------------------------------------------------------
__device__ __forceinline__ uint32_t smem_u32(const void* p) {
    uint32_t a;
    asm("{ .reg .u64 t; cvta.to.shared.u64 t, %1; cvt.u32.u64 %0, t; }" : "=r"(a) : "l"(p));
    return a;
}

#define CP_ASYNC16(smem, gmem) \
    asm volatile("cp.async.cg.shared.global [%0], [%1], 16;" :: "r"(smem), "l"(gmem))
#define CP_ASYNC_COMMIT() asm volatile("cp.async.commit_group;")
#define CP_ASYNC_WAIT(n)  asm volatile("cp.async.wait_group %0;" :: "n"(n))

#define LDMATRIX_X4(r0, r1, r2, r3, addr) \
    asm volatile("ldmatrix.sync.aligned.m8n8.x4.shared.b16 {%0,%1,%2,%3}, [%4];" \
        : "=r"(r0), "=r"(r1), "=r"(r2), "=r"(r3) : "r"(addr))

#define MMA16816(c, a, b0, b1) \
    asm volatile("mma.sync.aligned.m16n8k16.row.col.f32.f16.f16.f32 " \
        "{%0,%1,%2,%3}, {%4,%5,%6,%7}, {%8,%9}, {%0,%1,%2,%3};" \
        : "+f"((c)[0]), "+f"((c)[1]), "+f"((c)[2]), "+f"((c)[3]) \
        : "r"((a)[0]), "r"((a)[1]), "r"((a)[2]), "r"((a)[3]), "r"(b0), "r"(b1))

// ---------------- split: fp32 -> fp16 hi + fp16 lo ------------------------------
__device__ __forceinline__ void split4(float4 v, uint2& H, uint2& L) {
    __half h0 = __float2half_rn(v.x), h1 = __float2half_rn(v.y);
    __half h2 = __float2half_rn(v.z), h3 = __float2half_rn(v.w);
    __half2 ph0{h0, h1}, ph1{h2, h3};
    __half2 pl0{__float2half_rn(v.x - __half2float(h0)),
                __float2half_rn(v.y - __half2float(h1))};
    __half2 pl1{__float2half_rn(v.z - __half2float(h2)),
                __float2half_rn(v.w - __half2float(h3))};
    H.x = *(uint32_t*)&ph0; H.y = *(uint32_t*)&ph1;
    L.x = *(uint32_t*)&pl0; L.y = *(uint32_t*)&pl1;
}

#define X4   (MTOT * EDIM / 4)
#define W4   (EDIM * EDIM / 4)
#define ALL4 (X4 + 4 * W4)

__global__ void split_all_kernel(const float4* __restrict__ x,
                                 const float4* __restrict__ w0, const float4* __restrict__ w1,
                                 const float4* __restrict__ w2, const float4* __restrict__ w3,
                                 uint2* __restrict__ xhi, uint2* __restrict__ xlo,
                                 uint2* __restrict__ whi, uint2* __restrict__ wlo)
{
    int i = blockIdx.x * blockDim.x + threadIdx.x;
    if (i >= ALL4) return;
    uint2 H, L;
    if (i < X4) {
        split4(x[i], H, L);
        xhi[i] = H; xlo[i] = L;
    } else {
        int j = i - X4;
        int which = j >> 14;
        int idx = j & 16383;
        const float4* src = which == 0 ? w0 : which == 1 ? w1 : which == 2 ? w2 : w3;
        split4(src[idx], H, L);
        whi[j] = H; wlo[j] = L;
    }
}

// ---------------- HMMA GEMM ------------------------------------------------------
// CTA tile 128(M) x 64(N), BK=32, 2-stage cp.async double buffer.
// 8 warps in 4(m) x 2(n); warp tile 32x32. 3 CTAs/SM target.
#define BM 128
#define BN 64
#define BK 32
#define NKC (EDIM / BK)             // 8
#define GT 256
#define LDA 40                      // padded row stride (halves)
#define A_TILE (BM * LDA)           // 5120 halves
#define B_TILE (BN * LDA)           // 2560 halves
#define STAGE (2 * A_TILE + 2 * B_TILE)   // 15360 halves: Ah, Al, Wh, Wl
#define OFF_AH 0
#define OFF_AL A_TILE
#define OFF_WH (2 * A_TILE)
#define OFF_WL (2 * A_TILE + B_TILE)
#define SMEM_BYTES (2 * STAGE * 2 + 512)  // 61952

__device__ __forceinline__ void load_stage(uint32_t st,
                                           const __half* __restrict__ Ah,
                                           const __half* __restrict__ Al,
                                           const __half* __restrict__ Wh,
                                           const __half* __restrict__ Wl,
                                           int m0, int n0, int k0, int tid)
{
    // A: 128 rows x 32 halves (4 chunks/row) = 512 chunks, hi+lo
#pragma unroll
    for (int i = 0; i < 2; i++) {
        const int c = tid + i * GT;          // 0..511
        const int row = c >> 2;
        const int col = (c & 3) << 3;
        const uint32_t soff = (uint32_t)(row * LDA + col) * 2;
        const size_t aoff = (size_t)(m0 + row) * EDIM + k0 + col;
        CP_ASYNC16(st + OFF_AH * 2 + soff, Ah + aoff);
        CP_ASYNC16(st + OFF_AL * 2 + soff, Al + aoff);
    }
    // W: 64 rows x 32 halves = 256 chunks, hi+lo
    {
        const int c = tid;                   // 0..255
        const int row = c >> 2;
        const int col = (c & 3) << 3;
        const uint32_t soff = (uint32_t)(row * LDA + col) * 2;
        const size_t woff = (size_t)(n0 + row) * EDIM + k0 + col;
        CP_ASYNC16(st + OFF_WH * 2 + soff, Wh + woff);
        CP_ASYNC16(st + OFF_WL * 2 + soff, Wl + woff);
    }
}

__global__ __launch_bounds__(GT, 3)
void hmma_gemm_kernel(const __half* __restrict__ Ah,
                      const __half* __restrict__ Al,
                      const __half* __restrict__ Wh_all,
                      const __half* __restrict__ Wl_all,
                      const float* __restrict__ b0p,
                      const float* __restrict__ b1p,
                      const float* __restrict__ b2p,
                      float* __restrict__ o0,
                      float* __restrict__ o1,
                      float* __restrict__ o2,
                      int wbase)
{
    extern __shared__ __half smem[];
    const uint32_t sb = smem_u32(smem);
    float* sbias = (float*)(smem + 2 * STAGE);

    const int tid = threadIdx.x;
    const int wid = tid >> 5;
    const int lane = tid & 31;
    const int sel = blockIdx.x >> 2;               // weight select
    const int n0 = (blockIdx.x & 3) * BN;          // n tile
    const int m0 = blockIdx.y * BM;
    const int warp_m = (wid & 3) * 32;
    const int warp_n = (wid >> 2) * 32;

    const __half* Wh = Wh_all + (size_t)(wbase + sel) * EDIM * EDIM;
    const __half* Wl = Wl_all + (size_t)(wbase + sel) * EDIM * EDIM;
    const float* bias = sel == 0 ? b0p : (sel == 1 ? b1p : b2p);
    float* C = sel == 0 ? o0 : (sel == 1 ? o1 : o2);

    load_stage(sb, Ah, Al, Wh, Wl, m0, n0, 0, tid);
    CP_ASYNC_COMMIT();
    load_stage(sb + STAGE * 2, Ah, Al, Wh, Wl, m0, n0, BK, tid);
    CP_ASYNC_COMMIT();
    if (tid < BN) sbias[tid] = bias[n0 + tid];

    float acc[2][4][4];
#pragma unroll
    for (int i = 0; i < 2; i++)
#pragma unroll
        for (int j = 0; j < 4; j++)
#pragma unroll
            for (int r = 0; r < 4; r++) acc[i][j][r] = 0.0f;

    for (int kc = 0; kc < NKC; kc++) {
        if (kc < NKC - 1) CP_ASYNC_WAIT(1); else CP_ASYNC_WAIT(0);
        __syncthreads();

        const uint32_t st = sb + (kc & 1) * STAGE * 2;
        const uint32_t sAh = st + OFF_AH * 2;
        const uint32_t sAl = st + OFF_AL * 2;
        const uint32_t sWh = st + OFF_WH * 2;
        const uint32_t sWl = st + OFF_WL * 2;

#pragma unroll
        for (int ks = 0; ks < BK / 16; ks++) {
            const int k = ks * 16;
            uint32_t ah[2][4], al[2][4];
#pragma unroll
            for (int mf = 0; mf < 2; mf++) {
                const uint32_t off =
                    (uint32_t)((warp_m + mf * 16 + (lane & 15)) * LDA + k + ((lane >> 4) << 3)) * 2;
                LDMATRIX_X4(ah[mf][0], ah[mf][1], ah[mf][2], ah[mf][3], sAh + off);
                LDMATRIX_X4(al[mf][0], al[mf][1], al[mf][2], al[mf][3], sAl + off);
            }
#pragma unroll
            for (int nf = 0; nf < 2; nf++) {
                const uint32_t boff =
                    (uint32_t)((warp_n + nf * 16 + (lane & 7) + ((lane >> 4) << 3)) * LDA
                               + k + (((lane >> 3) & 1) << 3)) * 2;
                uint32_t bh[4], bl[4];
                LDMATRIX_X4(bh[0], bh[1], bh[2], bh[3], sWh + boff);
                LDMATRIX_X4(bl[0], bl[1], bl[2], bl[3], sWl + boff);
                float* a0 = acc[0][nf * 2];
                float* a1 = acc[0][nf * 2 + 1];
                float* a2 = acc[1][nf * 2];
                float* a3 = acc[1][nf * 2 + 1];
                MMA16816(a0, ah[0], bh[0], bh[1]);
                MMA16816(a1, ah[0], bh[2], bh[3]);
                MMA16816(a2, ah[1], bh[0], bh[1]);
                MMA16816(a3, ah[1], bh[2], bh[3]);
                MMA16816(a0, ah[0], bl[0], bl[1]);
                MMA16816(a1, ah[0], bl[2], bl[3]);
                MMA16816(a2, ah[1], bl[0], bl[1]);
                MMA16816(a3, ah[1], bl[2], bl[3]);
                MMA16816(a0, al[0], bh[0], bh[1]);
                MMA16816(a1, al[0], bh[2], bh[3]);
                MMA16816(a2, al[1], bh[0], bh[1]);
                MMA16816(a3, al[1], bh[2], bh[3]);
            }
        }
        __syncthreads();
        if (kc + 2 < NKC) {
            load_stage(st, Ah, Al, Wh, Wl, m0, n0, (kc + 2) * BK, tid);
            CP_ASYNC_COMMIT();
        }
    }

    // epilogue: C = acc + bias (bias from smem)
#pragma unroll
    for (int mf = 0; mf < 2; mf++) {
        const int r0 = m0 + warp_m + mf * 16 + (lane >> 2);
#pragma unroll
        for (int nf = 0; nf < 4; nf++) {
            const int colL = warp_n + nf * 8 + (lane & 3) * 2;
            const float b0 = sbias[colL], b1 = sbias[colL + 1];
            const int col = n0 + colL;
            float2 v0{acc[mf][nf][0] + b0, acc[mf][nf][1] + b1};
            float2 v1{acc[mf][nf][2] + b0, acc[mf][nf][3] + b1};
            *(float2*)(C + (size_t)r0 * EDIM + col) = v0;
            *(float2*)(C + (size_t)(r0 + 8) * EDIM + col) = v1;
        }
    }
}

// ---------------- attention over heads; fused y -> (yh, yl) fp16 split ----------
__global__ __launch_bounds__(256)
void attn_heads_kernel(const float* __restrict__ q,
                       const float* __restrict__ k,
                       const float* __restrict__ v,
                       __half* __restrict__ yh,
                       __half* __restrict__ yl)
{
    const int t = blockIdx.x * 8 + (threadIdx.x >> 5);
    const int lane = threadIdx.x & 31;

    const float2* qt = (const float2*)(q + (size_t)t * EDIM) + lane;
    const float2* kt = (const float2*)(k + (size_t)t * EDIM) + lane;
    const float2* vt = (const float2*)(v + (size_t)t * EDIM) + lane;

    float2 qv[HDIM], kv[HDIM], vv[HDIM];
#pragma unroll
    for (int h = 0; h < HDIM; h++) {
        qv[h] = qt[h * 32];
        kv[h] = kt[h * 32];
        vv[h] = vt[h * 32];
    }

    float s[HDIM][HDIM];
#pragma unroll
    for (int h = 0; h < HDIM; h++)
#pragma unroll
        for (int g = 0; g < HDIM; g++) {
            float p = qv[h].x * kv[g].x + qv[h].y * kv[g].y;
#pragma unroll
            for (int off = 16; off > 0; off >>= 1)
                p += __shfl_xor_sync(0xFFFFFFFFu, p, off);
            s[h][g] = p * 0.125f;
        }

    float p[HDIM][HDIM];
#pragma unroll
    for (int h = 0; h < HDIM; h++) {
        float m = s[h][0];
#pragma unroll
        for (int g = 1; g < HDIM; g++) m = fmaxf(m, s[h][g]);
        float sum = 0.0f;
#pragma unroll
        for (int g = 0; g < HDIM; g++) { p[h][g] = __expf(s[h][g] - m); sum += p[h][g]; }
        const float inv = 1.0f / sum;
#pragma unroll
        for (int g = 0; g < HDIM; g++) p[h][g] *= inv;
    }

    __half2* yhp = (__half2*)(yh + (size_t)t * EDIM) + lane;
    __half2* ylp = (__half2*)(yl + (size_t)t * EDIM) + lane;
#pragma unroll
    for (int h = 0; h < HDIM; h++) {
        float ax = 0.0f, ay = 0.0f;
#pragma unroll
        for (int g = 0; g < HDIM; g++) {
            ax = fmaf(p[h][g], vv[g].x, ax);
            ay = fmaf(p[h][g], vv[g].y, ay);
        }
        __half hx = __float2half_rn(ax), hy = __float2half_rn(ay);
        yhp[h * 32] = __half2{hx, hy};
        ylp[h * 32] = __half2{__float2half_rn(ax - __half2float(hx)),
                              __float2half_rn(ay - __half2float(hy))};
    }
}

// ---------------- launch --------------------------------------------------------
extern "C" void kernel_launch(void* const* d_in, const int* in_sizes, int n_in,
                              void* d_out, int out_size)
{
    const float* x  = (const float*)d_in[0];
    const float* Wq = (const float*)d_in[1];
    const float* bq = (const float*)d_in[2];
    const float* Wk = (const float*)d_in[3];
    const float* bk = (const float*)d_in[4];
    const float* Wv = (const float*)d_in[5];
    const float* bv = (const float*)d_in[6];
    const float* Wo = (const float*)d_in[7];
    const float* bo = (const float*)d_in[8];
    float* out = (float*)d_out;

    __half *xh, *xl, *yh, *yl;
    float *q, *k, *v;
    __half (*wh)[EDIM * EDIM], (*wl)[EDIM * EDIM];
    cudaGetSymbolAddress((void**)&xh, g_xh);
    cudaGetSymbolAddress((void**)&xl, g_xl);
    cudaGetSymbolAddress((void**)&yh, g_yh);
    cudaGetSymbolAddress((void**)&yl, g_yl);
    cudaGetSymbolAddress((void**)&q, g_q);
    cudaGetSymbolAddress((void**)&k, g_k);
    cudaGetSymbolAddress((void**)&v, g_v);
    cudaGetSymbolAddress((void**)&wh, g_wh);
    cudaGetSymbolAddress((void**)&wl, g_wl);

    cudaFuncSetAttribute(hmma_gemm_kernel,
                         cudaFuncAttributeMaxDynamicSharedMemorySize, SMEM_BYTES);

    split_all_kernel<<<(ALL4 + 255) / 256, 256>>>(
        (const float4*)x, (const float4*)Wq, (const float4*)Wk,
        (const float4*)Wv, (const float4*)Wo,
        (uint2*)xh, (uint2*)xl, (uint2*)wh[0], (uint2*)wl[0]);

    // fused Q,K,V GEMM: grid.x = 3 weights x 4 n-tiles
    {
        dim3 grid(12, MTOT / BM);
        hmma_gemm_kernel<<<grid, GT, SMEM_BYTES>>>(
            xh, xl, wh[0], wl[0], bq, bk, bv, q, k, v, 0);
    }

    attn_heads_kernel<<<MTOT / 8, 256>>>(q, k, v, yh, yl);

    // output GEMM: 4 n-tiles
    {
        dim3 grid(4, MTOT / BM);
        hmma_gemm_kernel<<<grid, GT, SMEM_BYTES>>>(
            yh, yl, wh[0], wl[0], bo, bo, bo, out, out, out, 3);
    }
}

// round 9
// speedup vs baseline: 1.2756x; 1.2232x over previous
#include <cuda_runtime.h>
#include <cuda_fp16.h>
#include <cstdint>

#define BDIM 8
#define SDIM 4096
#define EDIM 256
#define HDIM 4
#define DK   64
#define MTOT (BDIM * SDIM)   // 32768

// ---------------- scratch (device globals; no runtime alloc) -------------------
__device__ __half g_xh[(size_t)MTOT * EDIM];
__device__ __half g_xl[(size_t)MTOT * EDIM];
__device__ __half g_yh[(size_t)MTOT * EDIM];
__device__ __half g_yl[(size_t)MTOT * EDIM];
__device__ float  g_q[(size_t)MTOT * EDIM];
__device__ float  g_k[(size_t)MTOT * EDIM];
__device__ float  g_v[(size_t)MTOT * EDIM];
__device__ __half g_wh[4][EDIM * EDIM];

// ---------------- helpers ------------------------------------------------------
__device__ __forceinline__ uint32_t smem_u32(const void* p) {
    uint32_t a;
    asm("{ .reg .u64 t; cvta.to.shared.u64 t, %1; cvt.u32.u64 %0, t; }" : "=r"(a) : "l"(p));
    return a;
}

#define CP_ASYNC16(smem, gmem) \
    asm volatile("cp.async.cg.shared.global [%0], [%1], 16;" :: "r"(smem), "l"(gmem))
#define CP_ASYNC_COMMIT() asm volatile("cp.async.commit_group;")
#define CP_ASYNC_WAIT(n)  asm volatile("cp.async.wait_group %0;" :: "n"(n))

#define LDMATRIX_X4(r0, r1, r2, r3, addr) \
    asm volatile("ldmatrix.sync.aligned.m8n8.x4.shared.b16 {%0,%1,%2,%3}, [%4];" \
        : "=r"(r0), "=r"(r1), "=r"(r2), "=r"(r3) : "r"(addr))

#define MMA16816(c, a, b0, b1) \
    asm volatile("mma.sync.aligned.m16n8k16.row.col.f32.f16.f16.f32 " \
        "{%0,%1,%2,%3}, {%4,%5,%6,%7}, {%8,%9}, {%0,%1,%2,%3};" \
        : "+f"((c)[0]), "+f"((c)[1]), "+f"((c)[2]), "+f"((c)[3]) \
        : "r"((a)[0]), "r"((a)[1]), "r"((a)[2]), "r"((a)[3]), "r"(b0), "r"(b1))

// ---------------- split: x -> fp16 hi + lo; W -> fp16 hi only -------------------
__device__ __forceinline__ void split4(float4 v, uint2& H, uint2& L) {
    __half h0 = __float2half_rn(v.x), h1 = __float2half_rn(v.y);
    __half h2 = __float2half_rn(v.z), h3 = __float2half_rn(v.w);
    __half2 ph0{h0, h1}, ph1{h2, h3};
    __half2 pl0{__float2half_rn(v.x - __half2float(h0)),
                __float2half_rn(v.y - __half2float(h1))};
    __half2 pl1{__float2half_rn(v.z - __half2float(h2)),
                __float2half_rn(v.w - __half2float(h3))};
    H.x = *(uint32_t*)&ph0; H.y = *(uint32_t*)&ph1;
    L.x = *(uint32_t*)&pl0; L.y = *(uint32_t*)&pl1;
}

__device__ __forceinline__ uint2 cvt4(float4 v) {
    __half2 p0{__float2half_rn(v.x), __float2half_rn(v.y)};
    __half2 p1{__float2half_rn(v.z), __float2half_rn(v.w)};
    uint2 H;
    H.x = *(uint32_t*)&p0; H.y = *(uint32_t*)&p1;
    return H;
}

#define X4   (MTOT * EDIM / 4)
#define W4   (EDIM * EDIM / 4)
#define ALL4 (X4 + 4 * W4)

__global__ void split_all_kernel(const float4* __restrict__ x,
                                 const float4* __restrict__ w0, const float4* __restrict__ w1,
                                 const float4* __restrict__ w2, const float4* __restrict__ w3,
                                 uint2* __restrict__ xhi, uint2* __restrict__ xlo,
                                 uint2* __restrict__ whi)
{
    int i = blockIdx.x * blockDim.x + threadIdx.x;
    if (i >= ALL4) return;
    if (i < X4) {
        uint2 H, L;
        split4(x[i], H, L);
        xhi[i] = H; xlo[i] = L;
    } else {
        int j = i - X4;
        int which = j >> 14;
        int idx = j & 16383;
        const float4* src = which == 0 ? w0 : which == 1 ? w1 : which == 2 ? w2 : w3;
        whi[j] = cvt4(src[idx]);
    }
}

// ---------------- HMMA GEMM: C = (Ah + Al) * Wh^T + bias (2-term) ---------------
// CTA tile 128(M) x 64(N), BK=32, 2-stage cp.async double buffer.
// 8 warps in 4(m) x 2(n); warp tile 32x32.
#define BM 128
#define BN 64
#define BK 32
#define NKC (EDIM / BK)             // 8
#define GT 256
#define LDA 40                      // padded row stride (halves)
#define A_TILE (BM * LDA)           // 5120 halves
#define B_TILE (BN * LDA)           // 2560 halves
#define STAGE (2 * A_TILE + B_TILE) // 12800 halves: Ah, Al, Wh
#define OFF_AH 0
#define OFF_AL A_TILE
#define OFF_WH (2 * A_TILE)
#define SMEM_BYTES (2 * STAGE * 2 + 512)  // 51712

__device__ __forceinline__ void load_stage(uint32_t st,
                                           const __half* __restrict__ Ah,
                                           const __half* __restrict__ Al,
                                           const __half* __restrict__ Wh,
                                           int m0, int n0, int k0, int tid)
{
    // A: 128 rows x 32 halves = 512 chunks, hi+lo
#pragma unroll
    for (int i = 0; i < 2; i++) {
        const int c = tid + i * GT;
        const int row = c >> 2;
        const int col = (c & 3) << 3;
        const uint32_t soff = (uint32_t)(row * LDA + col) * 2;
        const size_t aoff = (size_t)(m0 + row) * EDIM + k0 + col;
        CP_ASYNC16(st + OFF_AH * 2 + soff, Ah + aoff);
        CP_ASYNC16(st + OFF_AL * 2 + soff, Al + aoff);
    }
    // W: 64 rows x 32 halves = 256 chunks, hi only
    {
        const int c = tid;
        const int row = c >> 2;
        const int col = (c & 3) << 3;
        const uint32_t soff = (uint32_t)(row * LDA + col) * 2;
        CP_ASYNC16(st + OFF_WH * 2 + soff, Wh + (size_t)(n0 + row) * EDIM + k0 + col);
    }
}

__global__ __launch_bounds__(GT, 3)
void hmma_gemm_kernel(const __half* __restrict__ Ah,
                      const __half* __restrict__ Al,
                      const __half* __restrict__ Wh_all,
                      const float* __restrict__ b0p,
                      const float* __restrict__ b1p,
                      const float* __restrict__ b2p,
                      float* __restrict__ o0,
                      float* __restrict__ o1,
                      float* __restrict__ o2,
                      int wbase)
{
    extern __shared__ __half smem[];
    const uint32_t sb = smem_u32(smem);
    float* sbias = (float*)(smem + 2 * STAGE);

    const int tid = threadIdx.x;
    const int wid = tid >> 5;
    const int lane = tid & 31;
    const int sel = blockIdx.x >> 2;
    const int n0 = (blockIdx.x & 3) * BN;
    const int m0 = blockIdx.y * BM;
    const int warp_m = (wid & 3) * 32;
    const int warp_n = (wid >> 2) * 32;

    const __half* Wh = Wh_all + (size_t)(wbase + sel) * EDIM * EDIM;
    const float* bias = sel == 0 ? b0p : (sel == 1 ? b1p : b2p);
    float* C = sel == 0 ? o0 : (sel == 1 ? o1 : o2);

    load_stage(sb, Ah, Al, Wh, m0, n0, 0, tid);
    CP_ASYNC_COMMIT();
    load_stage(sb + STAGE * 2, Ah, Al, Wh, m0, n0, BK, tid);
    CP_ASYNC_COMMIT();
    if (tid < BN) sbias[tid] = bias[n0 + tid];

    float acc[2][4][4];
#pragma unroll
    for (int i = 0; i < 2; i++)
#pragma unroll
        for (int j = 0; j < 4; j++)
#pragma unroll
            for (int r = 0; r < 4; r++) acc[i][j][r] = 0.0f;

    for (int kc = 0; kc < NKC; kc++) {
        if (kc < NKC - 1) CP_ASYNC_WAIT(1); else CP_ASYNC_WAIT(0);
        __syncthreads();

        const uint32_t st = sb + (kc & 1) * STAGE * 2;
        const uint32_t sAh = st + OFF_AH * 2;
        const uint32_t sAl = st + OFF_AL * 2;
        const uint32_t sWh = st + OFF_WH * 2;

#pragma unroll
        for (int ks = 0; ks < BK / 16; ks++) {
            const int k = ks * 16;
            uint32_t ah[2][4], al[2][4];
#pragma unroll
            for (int mf = 0; mf < 2; mf++) {
                const uint32_t off =
                    (uint32_t)((warp_m + mf * 16 + (lane & 15)) * LDA + k + ((lane >> 4) << 3)) * 2;
                LDMATRIX_X4(ah[mf][0], ah[mf][1], ah[mf][2], ah[mf][3], sAh + off);
                LDMATRIX_X4(al[mf][0], al[mf][1], al[mf][2], al[mf][3], sAl + off);
            }
#pragma unroll
            for (int nf = 0; nf < 2; nf++) {
                const uint32_t boff =
                    (uint32_t)((warp_n + nf * 16 + (lane & 7) + ((lane >> 4) << 3)) * LDA
                               + k + (((lane >> 3) & 1) << 3)) * 2;
                uint32_t bh[4];
                LDMATRIX_X4(bh[0], bh[1], bh[2], bh[3], sWh + boff);
                float* a0 = acc[0][nf * 2];
                float* a1 = acc[0][nf * 2 + 1];
                float* a2 = acc[1][nf * 2];
                float* a3 = acc[1][nf * 2 + 1];
                MMA16816(a0, ah[0], bh[0], bh[1]);
                MMA16816(a1, ah[0], bh[2], bh[3]);
                MMA16816(a2, ah[1], bh[0], bh[1]);
                MMA16816(a3, ah[1], bh[2], bh[3]);
                MMA16816(a0, al[0], bh[0], bh[1]);
                MMA16816(a1, al[0], bh[2], bh[3]);
                MMA16816(a2, al[1], bh[0], bh[1]);
                MMA16816(a3, al[1], bh[2], bh[3]);
            }
        }
        __syncthreads();
        if (kc + 2 < NKC) {
            load_stage(st, Ah, Al, Wh, m0, n0, (kc + 2) * BK, tid);
            CP_ASYNC_COMMIT();
        }
    }

    // epilogue: C = acc + bias
#pragma unroll
    for (int mf = 0; mf < 2; mf++) {
        const int r0 = m0 + warp_m + mf * 16 + (lane >> 2);
#pragma unroll
        for (int nf = 0; nf < 4; nf++) {
            const int colL = warp_n + nf * 8 + (lane & 3) * 2;
            const float b0 = sbias[colL], b1 = sbias[colL + 1];
            const int col = n0 + colL;
            float2 v0{acc[mf][nf][0] + b0, acc[mf][nf][1] + b1};
            float2 v1{acc[mf][nf][2] + b0, acc[mf][nf][3] + b1};
            *(float2*)(C + (size_t)r0 * EDIM + col) = v0;
            *(float2*)(C + (size_t)(r0 + 8) * EDIM + col) = v1;
        }
    }
}

// ---------------- attention over heads; fused y -> (yh, yl) fp16 split ----------
__global__ __launch_bounds__(256)
void attn_heads_kernel(const float* __restrict__ q,
                       const float* __restrict__ k,
                       const float* __restrict__ v,
                       __half* __restrict__ yh,
                       __half* __restrict__ yl)
{
    const int t = blockIdx.x * 8 + (threadIdx.x >> 5);
    const int lane = threadIdx.x & 31;

    const float2* qt = (const float2*)(q + (size_t)t * EDIM) + lane;
    const float2* kt = (const float2*)(k + (size_t)t * EDIM) + lane;
    const float2* vt = (const float2*)(v + (size_t)t * EDIM) + lane;

    float2 qv[HDIM], kv[HDIM], vv[HDIM];
#pragma unroll
    for (int h = 0; h < HDIM; h++) {
        qv[h] = qt[h * 32];
        kv[h] = kt[h * 32];
        vv[h] = vt[h * 32];
    }

    float s[HDIM][HDIM];
#pragma unroll
    for (int h = 0; h < HDIM; h++)
#pragma unroll
        for (int g = 0; g < HDIM; g++) {
            float p = qv[h].x * kv[g].x + qv[h].y * kv[g].y;
#pragma unroll
            for (int off = 16; off > 0; off >>= 1)
                p += __shfl_xor_sync(0xFFFFFFFFu, p, off);
            s[h][g] = p * 0.125f;
        }

    float p[HDIM][HDIM];
#pragma unroll
    for (int h = 0; h < HDIM; h++) {
        float m = s[h][0];
#pragma unroll
        for (int g = 1; g < HDIM; g++) m = fmaxf(m, s[h][g]);
        float sum = 0.0f;
#pragma unroll
        for (int g = 0; g < HDIM; g++) { p[h][g] = __expf(s[h][g] - m); sum += p[h][g]; }
        const float inv = 1.0f / sum;
#pragma unroll
        for (int g = 0; g < HDIM; g++) p[h][g] *= inv;
    }

    __half2* yhp = (__half2*)(yh + (size_t)t * EDIM) + lane;
    __half2* ylp = (__half2*)(yl + (size_t)t * EDIM) + lane;
#pragma unroll
    for (int h = 0; h < HDIM; h++) {
        float ax = 0.0f, ay = 0.0f;
#pragma unroll
        for (int g = 0; g < HDIM; g++) {
            ax = fmaf(p[h][g], vv[g].x, ax);
            ay = fmaf(p[h][g], vv[g].y, ay);
        }
        __half hx = __float2half_rn(ax), hy = __float2half_rn(ay);
        yhp[h * 32] = __half2{hx, hy};
        ylp[h * 32] = __half2{__float2half_rn(ax - __half2float(hx)),
                              __float2half_rn(ay - __half2float(hy))};
    }
}

// ---------------- launch --------------------------------------------------------
extern "C" void kernel_launch(void* const* d_in, const int* in_sizes, int n_in,
                              void* d_out, int out_size)
{
    const float* x  = (const float*)d_in[0];
    const float* Wq = (const float*)d_in[1];
    const float* bq = (const float*)d_in[2];
    const float* Wk = (const float*)d_in[3];
    const float* bk = (const float*)d_in[4];
    const float* Wv = (const float*)d_in[5];
    const float* bv = (const float*)d_in[6];
    const float* Wo = (const float*)d_in[7];
    const float* bo = (const float*)d_in[8];
    float* out = (float*)d_out;

    __half *xh, *xl, *yh, *yl;
    float *q, *k, *v;
    __half (*wh)[EDIM * EDIM];
    cudaGetSymbolAddress((void**)&xh, g_xh);
    cudaGetSymbolAddress((void**)&xl, g_xl);
    cudaGetSymbolAddress((void**)&yh, g_yh);
    cudaGetSymbolAddress((void**)&yl, g_yl);
    cudaGetSymbolAddress((void**)&q, g_q);
    cudaGetSymbolAddress((void**)&k, g_k);
    cudaGetSymbolAddress((void**)&v, g_v);
    cudaGetSymbolAddress((void**)&wh, g_wh);

    cudaFuncSetAttribute(hmma_gemm_kernel,
                         cudaFuncAttributeMaxDynamicSharedMemorySize, SMEM_BYTES);

    split_all_kernel<<<(ALL4 + 255) / 256, 256>>>(
        (const float4*)x, (const float4*)Wq, (const float4*)Wk,
        (const float4*)Wv, (const float4*)Wo,
        (uint2*)xh, (uint2*)xl, (uint2*)wh[0]);

    // fused Q,K,V GEMM: grid.x = 3 weights x 4 n-tiles
    {
        dim3 grid(12, MTOT / BM);
        hmma_gemm_kernel<<<grid, GT, SMEM_BYTES>>>(
            xh, xl, wh[0], bq, bk, bv, q, k, v, 0);
    }

    attn_heads_kernel<<<MTOT / 8, 256>>>(q, k, v, yh, yl);

    // output GEMM: 4 n-tiles
    {
        dim3 grid(4, MTOT / BM);
        hmma_gemm_kernel<<<grid, GT, SMEM_BYTES>>>(
            yh, yl, wh[0], bo, bo, bo, out, out, out, 3);
    }
}

// round 10
// speedup vs baseline: 1.7913x; 1.4043x over previous
#include <cuda_runtime.h>
#include <cuda_fp16.h>
#include <cstdint>

#define BDIM 8
#define SDIM 4096
#define EDIM 256
#define HDIM 4
#define DK   64
#define MTOT (BDIM * SDIM)   // 32768

// ---------------- scratch (device globals; no runtime alloc) -------------------
__device__ __half g_xh[(size_t)MTOT * EDIM];
__device__ __half g_yh[(size_t)MTOT * EDIM];
__device__ __half g_q[(size_t)MTOT * EDIM];
__device__ __half g_k[(size_t)MTOT * EDIM];
__device__ __half g_v[(size_t)MTOT * EDIM];
__device__ __half g_wh[4][EDIM * EDIM];

// ---------------- helpers ------------------------------------------------------
__device__ __forceinline__ uint32_t smem_u32(const void* p) {
    uint32_t a;
    asm("{ .reg .u64 t; cvta.to.shared.u64 t, %1; cvt.u32.u64 %0, t; }" : "=r"(a) : "l"(p));
    return a;
}

#define CP_ASYNC16(smem, gmem) \
    asm volatile("cp.async.cg.shared.global [%0], [%1], 16;" :: "r"(smem), "l"(gmem))
#define CP_ASYNC_COMMIT() asm volatile("cp.async.commit_group;")
#define CP_ASYNC_WAIT(n)  asm volatile("cp.async.wait_group %0;" :: "n"(n))

#define LDMATRIX_X4(r0, r1, r2, r3, addr) \
    asm volatile("ldmatrix.sync.aligned.m8n8.x4.shared.b16 {%0,%1,%2,%3}, [%4];" \
        : "=r"(r0), "=r"(r1), "=r"(r2), "=r"(r3) : "r"(addr))

#define MMA16816(c, a, b0, b1) \
    asm volatile("mma.sync.aligned.m16n8k16.row.col.f32.f16.f16.f32 " \
        "{%0,%1,%2,%3}, {%4,%5,%6,%7}, {%8,%9}, {%0,%1,%2,%3};" \
        : "+f"((c)[0]), "+f"((c)[1]), "+f"((c)[2]), "+f"((c)[3]) \
        : "r"((a)[0]), "r"((a)[1]), "r"((a)[2]), "r"((a)[3]), "r"(b0), "r"(b1))

// ---------------- convert fp32 -> fp16 ------------------------------------------
__device__ __forceinline__ uint2 cvt4(float4 v) {
    __half2 p0{__float2half_rn(v.x), __float2half_rn(v.y)};
    __half2 p1{__float2half_rn(v.z), __float2half_rn(v.w)};
    uint2 H;
    H.x = *(uint32_t*)&p0; H.y = *(uint32_t*)&p1;
    return H;
}

#define X4   (MTOT * EDIM / 4)
#define W4   (EDIM * EDIM / 4)
#define ALL4 (X4 + 4 * W4)

__global__ void split_all_kernel(const float4* __restrict__ x,
                                 const float4* __restrict__ w0, const float4* __restrict__ w1,
                                 const float4* __restrict__ w2, const float4* __restrict__ w3,
                                 uint2* __restrict__ xhi, uint2* __restrict__ whi)
{
    int i = blockIdx.x * blockDim.x + threadIdx.x;
    if (i >= ALL4) return;
    if (i < X4) {
        xhi[i] = cvt4(x[i]);
    } else {
        int j = i - X4;
        int which = j >> 14;
        int idx = j & 16383;
        const float4* src = which == 0 ? w0 : which == 1 ? w1 : which == 2 ? w2 : w3;
        whi[j] = cvt4(src[idx]);
    }
}

// ---------------- HMMA GEMM: C = A * W^T + bias (plain fp16, fp32 accum) --------
// CTA tile 128(M) x 64(N), BK=32, 2-stage cp.async double buffer.
// 8 warps in 4(m) x 2(n); warp tile 32x32. Target 4 CTAs/SM.
#define BM 128
#define BN 64
#define BK 32
#define NKC (EDIM / BK)             // 8
#define GT 256
#define LDA 40                      // padded row stride (halves)
#define A_TILE (BM * LDA)           // 5120 halves
#define B_TILE (BN * LDA)           // 2560 halves
#define STAGE (A_TILE + B_TILE)     // 7680 halves
#define OFF_A 0
#define OFF_W A_TILE
#define SMEM_BYTES (2 * STAGE * 2 + 512)   // 31232

__device__ __forceinline__ void load_stage(uint32_t st,
                                           const __half* __restrict__ A,
                                           const __half* __restrict__ W,
                                           int m0, int n0, int k0, int tid)
{
    // A: 128 rows x 32 halves = 512 chunks (2/thread)
#pragma unroll
    for (int i = 0; i < 2; i++) {
        const int c = tid + i * GT;
        const int row = c >> 2;
        const int col = (c & 3) << 3;
        CP_ASYNC16(st + OFF_A * 2 + (uint32_t)(row * LDA + col) * 2,
                   A + (size_t)(m0 + row) * EDIM + k0 + col);
    }
    // W: 64 rows x 32 halves = 256 chunks (1/thread)
    {
        const int row = tid >> 2;
        const int col = (tid & 3) << 3;
        CP_ASYNC16(st + OFF_W * 2 + (uint32_t)(row * LDA + col) * 2,
                   W + (size_t)(n0 + row) * EDIM + k0 + col);
    }
}

template <typename OT>
__global__ __launch_bounds__(GT, 4)
void hmma_gemm_kernel(const __half* __restrict__ A,
                      const __half* __restrict__ Wh_all,
                      const float* __restrict__ b0p,
                      const float* __restrict__ b1p,
                      const float* __restrict__ b2p,
                      OT* __restrict__ o0,
                      OT* __restrict__ o1,
                      OT* __restrict__ o2,
                      int wbase)
{
    extern __shared__ __half smem[];
    const uint32_t sb = smem_u32(smem);
    float* sbias = (float*)(smem + 2 * STAGE);

    const int tid = threadIdx.x;
    const int wid = tid >> 5;
    const int lane = tid & 31;
    const int sel = blockIdx.x >> 2;
    const int n0 = (blockIdx.x & 3) * BN;
    const int m0 = blockIdx.y * BM;
    const int warp_m = (wid & 3) * 32;
    const int warp_n = (wid >> 2) * 32;

    const __half* W = Wh_all + (size_t)(wbase + sel) * EDIM * EDIM;
    const float* bias = sel == 0 ? b0p : (sel == 1 ? b1p : b2p);
    OT* C = sel == 0 ? o0 : (sel == 1 ? o1 : o2);

    load_stage(sb, A, W, m0, n0, 0, tid);
    CP_ASYNC_COMMIT();
    load_stage(sb + STAGE * 2, A, W, m0, n0, BK, tid);
    CP_ASYNC_COMMIT();
    if (tid < BN) sbias[tid] = bias[n0 + tid];

    float acc[2][4][4];
#pragma unroll
    for (int i = 0; i < 2; i++)
#pragma unroll
        for (int j = 0; j < 4; j++)
#pragma unroll
            for (int r = 0; r < 4; r++) acc[i][j][r] = 0.0f;

    for (int kc = 0; kc < NKC; kc++) {
        if (kc < NKC - 1) CP_ASYNC_WAIT(1); else CP_ASYNC_WAIT(0);
        __syncthreads();

        const uint32_t st = sb + (kc & 1) * STAGE * 2;
        const uint32_t sA = st + OFF_A * 2;
        const uint32_t sW = st + OFF_W * 2;

#pragma unroll
        for (int ks = 0; ks < BK / 16; ks++) {
            const int k = ks * 16;
            uint32_t ah[2][4];
#pragma unroll
            for (int mf = 0; mf < 2; mf++) {
                const uint32_t off =
                    (uint32_t)((warp_m + mf * 16 + (lane & 15)) * LDA + k + ((lane >> 4) << 3)) * 2;
                LDMATRIX_X4(ah[mf][0], ah[mf][1], ah[mf][2], ah[mf][3], sA + off);
            }
#pragma unroll
            for (int nf = 0; nf < 2; nf++) {
                const uint32_t boff =
                    (uint32_t)((warp_n + nf * 16 + (lane & 7) + ((lane >> 4) << 3)) * LDA
                               + k + (((lane >> 3) & 1) << 3)) * 2;
                uint32_t bh[4];
                LDMATRIX_X4(bh[0], bh[1], bh[2], bh[3], sW + boff);
                MMA16816(acc[0][nf * 2],     ah[0], bh[0], bh[1]);
                MMA16816(acc[0][nf * 2 + 1], ah[0], bh[2], bh[3]);
                MMA16816(acc[1][nf * 2],     ah[1], bh[0], bh[1]);
                MMA16816(acc[1][nf * 2 + 1], ah[1], bh[2], bh[3]);
            }
        }
        __syncthreads();
        if (kc + 2 < NKC) {
            load_stage(st, A, W, m0, n0, (kc + 2) * BK, tid);
            CP_ASYNC_COMMIT();
        }
    }

    // epilogue: C = acc + bias
#pragma unroll
    for (int mf = 0; mf < 2; mf++) {
        const int r0 = m0 + warp_m + mf * 16 + (lane >> 2);
#pragma unroll
        for (int nf = 0; nf < 4; nf++) {
            const int colL = warp_n + nf * 8 + (lane & 3) * 2;
            const float b0 = sbias[colL], b1 = sbias[colL + 1];
            const int col = n0 + colL;
            float2 v0{acc[mf][nf][0] + b0, acc[mf][nf][1] + b1};
            float2 v1{acc[mf][nf][2] + b0, acc[mf][nf][3] + b1};
            if (sizeof(OT) == 2) {
                __half2 h0{__float2half_rn(v0.x), __float2half_rn(v0.y)};
                __half2 h1{__float2half_rn(v1.x), __float2half_rn(v1.y)};
                *(__half2*)((__half*)C + (size_t)r0 * EDIM + col) = h0;
                *(__half2*)((__half*)C + (size_t)(r0 + 8) * EDIM + col) = h1;
            } else {
                *(float2*)((float*)C + (size_t)r0 * EDIM + col) = v0;
                *(float2*)((float*)C + (size_t)(r0 + 8) * EDIM + col) = v1;
            }
        }
    }
}

// ---------------- attention over heads (fp16 in, fp16 out, fp32 math) -----------
__global__ __launch_bounds__(256)
void attn_heads_kernel(const __half* __restrict__ q,
                       const __half* __restrict__ k,
                       const __half* __restrict__ v,
                       __half* __restrict__ yh)
{
    const int t = blockIdx.x * 8 + (threadIdx.x >> 5);
    const int lane = threadIdx.x & 31;

    const __half2* qt = (const __half2*)(q + (size_t)t * EDIM) + lane;
    const __half2* kt = (const __half2*)(k + (size_t)t * EDIM) + lane;
    const __half2* vt = (const __half2*)(v + (size_t)t * EDIM) + lane;

    float2 qv[HDIM], kv[HDIM], vv[HDIM];
#pragma unroll
    for (int h = 0; h < HDIM; h++) {
        qv[h] = __half22float2(qt[h * 32]);
        kv[h] = __half22float2(kt[h * 32]);
        vv[h] = __half22float2(vt[h * 32]);
    }

    float s[HDIM][HDIM];
#pragma unroll
    for (int h = 0; h < HDIM; h++)
#pragma unroll
        for (int g = 0; g < HDIM; g++) {
            float p = qv[h].x * kv[g].x + qv[h].y * kv[g].y;
#pragma unroll
            for (int off = 16; off > 0; off >>= 1)
                p += __shfl_xor_sync(0xFFFFFFFFu, p, off);
            s[h][g] = p * 0.125f;
        }

    float p[HDIM][HDIM];
#pragma unroll
    for (int h = 0; h < HDIM; h++) {
        float m = s[h][0];
#pragma unroll
        for (int g = 1; g < HDIM; g++) m = fmaxf(m, s[h][g]);
        float sum = 0.0f;
#pragma unroll
        for (int g = 0; g < HDIM; g++) { p[h][g] = __expf(s[h][g] - m); sum += p[h][g]; }
        const float inv = 1.0f / sum;
#pragma unroll
        for (int g = 0; g < HDIM; g++) p[h][g] *= inv;
    }

    __half2* yhp = (__half2*)(yh + (size_t)t * EDIM) + lane;
#pragma unroll
    for (int h = 0; h < HDIM; h++) {
        float ax = 0.0f, ay = 0.0f;
#pragma unroll
        for (int g = 0; g < HDIM; g++) {
            ax = fmaf(p[h][g], vv[g].x, ax);
            ay = fmaf(p[h][g], vv[g].y, ay);
        }
        yhp[h * 32] = __half2{__float2half_rn(ax), __float2half_rn(ay)};
    }
}

// ---------------- launch --------------------------------------------------------
extern "C" void kernel_launch(void* const* d_in, const int* in_sizes, int n_in,
                              void* d_out, int out_size)
{
    const float* x  = (const float*)d_in[0];
    const float* Wq = (const float*)d_in[1];
    const float* bq = (const float*)d_in[2];
    const float* Wk = (const float*)d_in[3];
    const float* bk = (const float*)d_in[4];
    const float* Wv = (const float*)d_in[5];
    const float* bv = (const float*)d_in[6];
    const float* Wo = (const float*)d_in[7];
    const float* bo = (const float*)d_in[8];
    float* out = (float*)d_out;

    __half *xh, *yh, *q, *k, *v;
    __half (*wh)[EDIM * EDIM];
    cudaGetSymbolAddress((void**)&xh, g_xh);
    cudaGetSymbolAddress((void**)&yh, g_yh);
    cudaGetSymbolAddress((void**)&q, g_q);
    cudaGetSymbolAddress((void**)&k, g_k);
    cudaGetSymbolAddress((void**)&v, g_v);
    cudaGetSymbolAddress((void**)&wh, g_wh);

    cudaFuncSetAttribute(hmma_gemm_kernel<__half>,
                         cudaFuncAttributeMaxDynamicSharedMemorySize, SMEM_BYTES);
    cudaFuncSetAttribute(hmma_gemm_kernel<float>,
                         cudaFuncAttributeMaxDynamicSharedMemorySize, SMEM_BYTES);

    split_all_kernel<<<(ALL4 + 255) / 256, 256>>>(
        (const float4*)x, (const float4*)Wq, (const float4*)Wk,
        (const float4*)Wv, (const float4*)Wo,
        (uint2*)xh, (uint2*)wh[0]);

    // fused Q,K,V GEMM: grid.x = 3 weights x 4 n-tiles; fp16 outputs
    {
        dim3 grid(12, MTOT / BM);
        hmma_gemm_kernel<__half><<<grid, GT, SMEM_BYTES>>>(
            xh, wh[0], bq, bk, bv, q, k, v, 0);
    }

    attn_heads_kernel<<<MTOT / 8, 256>>>(q, k, v, yh);

    // output GEMM: fp32 output to d_out
    {
        dim3 grid(4, MTOT / BM);
        hmma_gemm_kernel<float><<<grid, GT, SMEM_BYTES>>>(
            yh, wh[0], bo, bo, bo, out, out, out, 3);
    }
}

// round 12
// speedup vs baseline: 1.8523x; 1.0340x over previous
#include <cuda_runtime.h>
#include <cuda_fp16.h>
#include <cstdint>

#define BDIM 8
#define SDIM 4096
#define EDIM 256
#define HDIM 4
#define DK   64
#define MTOT (BDIM * SDIM)   // 32768

// ---------------- scratch (device globals; no runtime alloc) -------------------
__device__ __half g_xh[(size_t)MTOT * EDIM];
__device__ __half g_yh[(size_t)MTOT * EDIM];
__device__ __half g_q[(size_t)MTOT * EDIM];
__device__ __half g_k[(size_t)MTOT * EDIM];
__device__ __half g_v[(size_t)MTOT * EDIM];
__device__ __half g_wh[4][EDIM * EDIM];

// ---------------- helpers ------------------------------------------------------
__device__ __forceinline__ uint32_t smem_u32(const void* p) {
    uint32_t a;
    asm("{ .reg .u64 t; cvta.to.shared.u64 t, %1; cvt.u32.u64 %0, t; }" : "=r"(a) : "l"(p));
    return a;
}

#define CP_ASYNC16(smem, gmem) \
    asm volatile("cp.async.cg.shared.global [%0], [%1], 16;" :: "r"(smem), "l"(gmem))
#define CP_ASYNC_COMMIT() asm volatile("cp.async.commit_group;")
#define CP_ASYNC_WAIT(n)  asm volatile("cp.async.wait_group %0;" :: "n"(n))

#define LDMATRIX_X4(r0, r1, r2, r3, addr) \
    asm volatile("ldmatrix.sync.aligned.m8n8.x4.shared.b16 {%0,%1,%2,%3}, [%4];" \
        : "=r"(r0), "=r"(r1), "=r"(r2), "=r"(r3) : "r"(addr))

#define MMA16816(c, a, b0, b1) \
    asm volatile("mma.sync.aligned.m16n8k16.row.col.f32.f16.f16.f32 " \
        "{%0,%1,%2,%3}, {%4,%5,%6,%7}, {%8,%9}, {%0,%1,%2,%3};" \
        : "+f"((c)[0]), "+f"((c)[1]), "+f"((c)[2]), "+f"((c)[3]) \
        : "r"((a)[0]), "r"((a)[1]), "r"((a)[2]), "r"((a)[3]), "r"(b0), "r"(b1))

// ---------------- convert fp32 -> fp16 ------------------------------------------
__device__ __forceinline__ uint2 cvt4(float4 v) {
    __half2 p0{__float2half_rn(v.x), __float2half_rn(v.y)};
    __half2 p1{__float2half_rn(v.z), __float2half_rn(v.w)};
    uint2 H;
    H.x = *(uint32_t*)&p0; H.y = *(uint32_t*)&p1;
    return H;
}

#define X4   (MTOT * EDIM / 4)
#define W4   (EDIM * EDIM / 4)
#define ALL4 (X4 + 4 * W4)

__global__ void split_all_kernel(const float4* __restrict__ x,
                                 const float4* __restrict__ w0, const float4* __restrict__ w1,
                                 const float4* __restrict__ w2, const float4* __restrict__ w3,
                                 uint2* __restrict__ xhi, uint2* __restrict__ whi)
{
    int i = blockIdx.x * blockDim.x + threadIdx.x;
    if (i >= ALL4) return;
    if (i < X4) {
        xhi[i] = cvt4(x[i]);
    } else {
        int j = i - X4;
        int which = j >> 14;
        int idx = j & 16383;
        const float4* src = which == 0 ? w0 : which == 1 ? w1 : which == 2 ? w2 : w3;
        whi[j] = cvt4(src[idx]);
    }
}

// ---------------- HMMA GEMM: C = A * W^T + bias (fp16 in, fp32 accum) -----------
// CTA tile 128(M) x 64(N), BK=64, 2-stage cp.async double buffer.
// 8 warps in 4(m) x 2(n); warp tile 32x32.
#define BM 128
#define BN 64
#define BK 64
#define NKC (EDIM / BK)             // 4
#define GT 256
#define LDA 72                      // padded row stride (halves)
#define A_TILE (BM * LDA)           // 9216 halves
#define B_TILE (BN * LDA)           // 4608 halves
#define STAGE (A_TILE + B_TILE)     // 13824 halves = 27648 B
#define OFF_A 0
#define OFF_W A_TILE
#define SMEM_BYTES (2 * STAGE * 2 + 512)   // 55808

__device__ __forceinline__ void load_stage(uint32_t st,
                                           const __half* __restrict__ A,
                                           const __half* __restrict__ W,
                                           int m0, int n0, int k0, int tid)
{
    // A: 128 rows x 64 halves = 1024 16B-chunks (4/thread)
#pragma unroll
    for (int i = 0; i < 4; i++) {
        const int c = tid + i * GT;
        const int row = c >> 3;
        const int col = (c & 7) << 3;
        CP_ASYNC16(st + OFF_A * 2 + (uint32_t)(row * LDA + col) * 2,
                   A + (size_t)(m0 + row) * EDIM + k0 + col);
    }
    // W: 64 rows x 64 halves = 512 chunks (2/thread)
#pragma unroll
    for (int i = 0; i < 2; i++) {
        const int c = tid + i * GT;
        const int row = c >> 3;
        const int col = (c & 7) << 3;
        CP_ASYNC16(st + OFF_W * 2 + (uint32_t)(row * LDA + col) * 2,
                   W + (size_t)(n0 + row) * EDIM + k0 + col);
    }
}

template <typename OT>
__global__ __launch_bounds__(GT, 4)
void hmma_gemm_kernel(const __half* __restrict__ A,
                      const __half* __restrict__ Wh_all,
                      const float* __restrict__ b0p,
                      const float* __restrict__ b1p,
                      const float* __restrict__ b2p,
                      OT* __restrict__ o0,
                      OT* __restrict__ o1,
                      OT* __restrict__ o2,
                      int wbase)
{
    extern __shared__ __half smem[];
    const uint32_t sb = smem_u32(smem);
    float* sbias = (float*)(smem + 2 * STAGE);

    const int tid = threadIdx.x;
    const int wid = tid >> 5;
    const int lane = tid & 31;
    const int sel = blockIdx.x >> 2;
    const int n0 = (blockIdx.x & 3) * BN;
    const int m0 = blockIdx.y * BM;
    const int warp_m = (wid & 3) * 32;
    const int warp_n = (wid >> 2) * 32;

    const __half* W = Wh_all + (size_t)(wbase + sel) * EDIM * EDIM;
    const float* bias = sel == 0 ? b0p : (sel == 1 ? b1p : b2p);
    OT* C = sel == 0 ? o0 : (sel == 1 ? o1 : o2);

    load_stage(sb, A, W, m0, n0, 0, tid);
    CP_ASYNC_COMMIT();
    load_stage(sb + STAGE * 2, A, W, m0, n0, BK, tid);
    CP_ASYNC_COMMIT();
    if (tid < BN) sbias[tid] = bias[n0 + tid];

    float acc[2][4][4];
#pragma unroll
    for (int i = 0; i < 2; i++)
#pragma unroll
        for (int j = 0; j < 4; j++)
#pragma unroll
            for (int r = 0; r < 4; r++) acc[i][j][r] = 0.0f;

    for (int kc = 0; kc < NKC; kc++) {
        if (kc < NKC - 1) CP_ASYNC_WAIT(1); else CP_ASYNC_WAIT(0);
        __syncthreads();

        const uint32_t st = sb + (kc & 1) * STAGE * 2;
        const uint32_t sA = st + OFF_A * 2;
        const uint32_t sW = st + OFF_W * 2;

#pragma unroll
        for (int ks = 0; ks < BK / 16; ks++) {
            const int k = ks * 16;
            uint32_t ah[2][4];
#pragma unroll
            for (int mf = 0; mf < 2; mf++) {
                const uint32_t off =
                    (uint32_t)((warp_m + mf * 16 + (lane & 15)) * LDA + k + ((lane >> 4) << 3)) * 2;
                LDMATRIX_X4(ah[mf][0], ah[mf][1], ah[mf][2], ah[mf][3], sA + off);
            }
#pragma unroll
            for (int nf = 0; nf < 2; nf++) {
                const uint32_t boff =
                    (uint32_t)((warp_n + nf * 16 + (lane & 7) + ((lane >> 4) << 3)) * LDA
                               + k + (((lane >> 3) & 1) << 3)) * 2;
                uint32_t bh[4];
                LDMATRIX_X4(bh[0], bh[1], bh[2], bh[3], sW + boff);
                MMA16816(acc[0][nf * 2],     ah[0], bh[0], bh[1]);
                MMA16816(acc[0][nf * 2 + 1], ah[0], bh[2], bh[3]);
                MMA16816(acc[1][nf * 2],     ah[1], bh[0], bh[1]);
                MMA16816(acc[1][nf * 2 + 1], ah[1], bh[2], bh[3]);
            }
        }
        __syncthreads();
        if (kc + 2 < NKC) {
            load_stage(st, A, W, m0, n0, (kc + 2) * BK, tid);
            CP_ASYNC_COMMIT();
        }
    }

    // epilogue: C = acc + bias
#pragma unroll
    for (int mf = 0; mf < 2; mf++) {
        const int r0 = m0 + warp_m + mf * 16 + (lane >> 2);
#pragma unroll
        for (int nf = 0; nf < 4; nf++) {
            const int colL = warp_n + nf * 8 + (lane & 3) * 2;
            const float b0 = sbias[colL], b1 = sbias[colL + 1];
            const int col = n0 + colL;
            float2 v0{acc[mf][nf][0] + b0, acc[mf][nf][1] + b1};
            float2 v1{acc[mf][nf][2] + b0, acc[mf][nf][3] + b1};
            if (sizeof(OT) == 2) {
                __half2 h0{__float2half_rn(v0.x), __float2half_rn(v0.y)};
                __half2 h1{__float2half_rn(v1.x), __float2half_rn(v1.y)};
                *(__half2*)((__half*)C + (size_t)r0 * EDIM + col) = h0;
                *(__half2*)((__half*)C + (size_t)(r0 + 8) * EDIM + col) = h1;
            } else {
                *(float2*)((float*)C + (size_t)r0 * EDIM + col) = v0;
                *(float2*)((float*)C + (size_t)(r0 + 8) * EDIM + col) = v1;
            }
        }
    }
}

// ---------------- attention over heads (fp16 in, fp16 out, fp32 math) -----------
__global__ __launch_bounds__(256)
void attn_heads_kernel(const __half* __restrict__ q,
                       const __half* __restrict__ k,
                       const __half* __restrict__ v,
                       __half* __restrict__ yh)
{
    const int t = blockIdx.x * 8 + (threadIdx.x >> 5);
    const int lane = threadIdx.x & 31;

    const __half2* qt = (const __half2*)(q + (size_t)t * EDIM) + lane;
    const __half2* kt = (const __half2*)(k + (size_t)t * EDIM) + lane;
    const __half2* vt = (const __half2*)(v + (size_t)t * EDIM) + lane;

    float2 qv[HDIM], kv[HDIM], vv[HDIM];
#pragma unroll
    for (int h = 0; h < HDIM; h++) {
        qv[h] = __half22float2(qt[h * 32]);
        kv[h] = __half22float2(kt[h * 32]);
        vv[h] = __half22float2(vt[h * 32]);
    }

    float s[HDIM][HDIM];
#pragma unroll
    for (int h = 0; h < HDIM; h++)
#pragma unroll
        for (int g = 0; g < HDIM; g++) {
            float p = qv[h].x * kv[g].x + qv[h].y * kv[g].y;
#pragma unroll
            for (int off = 16; off > 0; off >>= 1)
                p += __shfl_xor_sync(0xFFFFFFFFu, p, off);
            s[h][g] = p * 0.125f;
        }

    float p[HDIM][HDIM];
#pragma unroll
    for (int h = 0; h < HDIM; h++) {
        float m = s[h][0];
#pragma unroll
        for (int g = 1; g < HDIM; g++) m = fmaxf(m, s[h][g]);
        float sum = 0.0f;
#pragma unroll
        for (int g = 0; g < HDIM; g++) { p[h][g] = __expf(s[h][g] - m); sum += p[h][g]; }
        const float inv = 1.0f / sum;
#pragma unroll
        for (int g = 0; g < HDIM; g++) p[h][g] *= inv;
    }

    __half2* yhp = (__half2*)(yh + (size_t)t * EDIM) + lane;
#pragma unroll
    for (int h = 0; h < HDIM; h++) {
        float ax = 0.0f, ay = 0.0f;
#pragma unroll
        for (int g = 0; g < HDIM; g++) {
            ax = fmaf(p[h][g], vv[g].x, ax);
            ay = fmaf(p[h][g], vv[g].y, ay);
        }
        yhp[h * 32] = __half2{__float2half_rn(ax), __float2half_rn(ay)};
    }
}

// ---------------- launch --------------------------------------------------------
extern "C" void kernel_launch(void* const* d_in, const int* in_sizes, int n_in,
                              void* d_out, int out_size)
{
    const float* x  = (const float*)d_in[0];
    const float* Wq = (const float*)d_in[1];
    const float* bq = (const float*)d_in[2];
    const float* Wk = (const float*)d_in[3];
    const float* bk = (const float*)d_in[4];
    const float* Wv = (const float*)d_in[5];
    const float* bv = (const float*)d_in[6];
    const float* Wo = (const float*)d_in[7];
    const float* bo = (const float*)d_in[8];
    float* out = (float*)d_out;

    __half *xh, *yh, *q, *k, *v;
    __half (*wh)[EDIM * EDIM];
    cudaGetSymbolAddress((void**)&xh, g_xh);
    cudaGetSymbolAddress((void**)&yh, g_yh);
    cudaGetSymbolAddress((void**)&q, g_q);
    cudaGetSymbolAddress((void**)&k, g_k);
    cudaGetSymbolAddress((void**)&v, g_v);
    cudaGetSymbolAddress((void**)&wh, g_wh);

    cudaFuncSetAttribute(hmma_gemm_kernel<__half>,
                         cudaFuncAttributeMaxDynamicSharedMemorySize, SMEM_BYTES);
    cudaFuncSetAttribute(hmma_gemm_kernel<float>,
                         cudaFuncAttributeMaxDynamicSharedMemorySize, SMEM_BYTES);

    split_all_kernel<<<(ALL4 + 255) / 256, 256>>>(
        (const float4*)x, (const float4*)Wq, (const float4*)Wk,
        (const float4*)Wv, (const float4*)Wo,
        (uint2*)xh, (uint2*)wh[0]);

    // fused Q,K,V GEMM: grid.x = 3 weights x 4 n-tiles; fp16 outputs
    {
        dim3 grid(12, MTOT / BM);
        hmma_gemm_kernel<__half><<<grid, GT, SMEM_BYTES>>>(
            xh, wh[0], bq, bk, bv, q, k, v, 0);
    }

    attn_heads_kernel<<<MTOT / 8, 256>>>(q, k, v, yh);

    // output GEMM: fp32 output to d_out
    {
        dim3 grid(4, MTOT / BM);
        hmma_gemm_kernel<float><<<grid, GT, SMEM_BYTES>>>(
            yh, wh[0], bo, bo, bo, out, out, out, 3);
    }
}